// round 14
// baseline (speedup 1.0000x reference)
#include <cuda_runtime.h>

// TriplesDistances: B=16, N=512, A=1024
// inputs: positions f32 [B,N,3]; neighbors_j/k int32 [B,N,A]
// out layout: [r_ij | r_ik | r_jk], each B*N*A float32
#define NB 16
#define NN 512
#define NA 1024
#define THREADS 256
#define ROWS 4   // rows (n values) per block, same batch

#define TOTAL (NB * NN * NA)   // 8388608, fits int32

// Single-instruction MUFU.SQRT: sqrt.approx(0)=0 handles the safe-norm zero
// case with no select; rel err ~2^-20 << 1e-3 tolerance.
__device__ __forceinline__ float fast_sqrt(float s) {
    float r;
    asm("sqrt.approx.f32 %0, %1;" : "=f"(r) : "f"(s));
    return r;
}

__device__ __forceinline__ float dist3(float2 axy, float az, float2 bxy, float bz) {
    float dx = axy.x - bxy.x;
    float dy = axy.y - bxy.y;
    float dz = az - bz;
    float s = fmaf(dx, dx, fmaf(dy, dy, dz * dz));
    return fast_sqrt(s);
}

__global__ __launch_bounds__(THREADS, 6)
void TriplesDistances_kernel(const float* __restrict__ pos,
                             const int* __restrict__ nj,
                             const int* __restrict__ nk,
                             float* __restrict__ out) {
    __shared__ float2 spxy[NN];  // 4 KB
    __shared__ float  spz[NN];   // 2 KB

    const unsigned blk = blockIdx.x;                 // 0 .. NB*NN/ROWS-1
    const unsigned b   = blk / (NN / ROWS);          // batch
    const unsigned n0  = (blk % (NN / ROWS)) * ROWS; // first row in batch
    const unsigned t   = threadIdx.x;

    const unsigned a0    = t * 4u;
    const unsigned base0 = (b * NN + n0) * NA + a0;  // 32-bit safe

    // Row-0 index loads issued BEFORE staging: DRAM latency overlaps staging+sync
    int4 j4 = __ldcs(reinterpret_cast<const int4*>(nj + base0));
    int4 k4 = __ldcs(reinterpret_cast<const int4*>(nk + base0));

    // Cooperative stage of batch-b positions into smem (SoA)
    const float* pb = pos + b * (NN * 3);
    #pragma unroll
    for (unsigned i = t; i < NN; i += THREADS) {
        float x = pb[i * 3 + 0];
        float y = pb[i * 3 + 1];
        float z = pb[i * 3 + 2];
        spxy[i] = make_float2(x, y);
        spz[i]  = z;
    }
    __syncthreads();

    #pragma unroll
    for (unsigned r = 0; r < ROWS; r++) {
        const unsigned base = base0 + r * NA;
        const int4 jc = j4, kc = k4;

        // Prefetch next row's indices while current gathers are in flight
        if (r + 1 < ROWS) {
            j4 = __ldcs(reinterpret_cast<const int4*>(nj + base + NA));
            k4 = __ldcs(reinterpret_cast<const int4*>(nk + base + NA));
        }

        const float2 pixy = spxy[n0 + r];
        const float  piz  = spz[n0 + r];

        float4 rij, rik, rjk;

        // Two-element gather hoisting: 8 independent LDS in flight per group
        {
            float2 pj0 = spxy[jc.x]; float pj0z = spz[jc.x];
            float2 pk0 = spxy[kc.x]; float pk0z = spz[kc.x];
            float2 pj1 = spxy[jc.y]; float pj1z = spz[jc.y];
            float2 pk1 = spxy[kc.y]; float pk1z = spz[kc.y];
            rij.x = dist3(pj0, pj0z, pixy, piz);
            rik.x = dist3(pk0, pk0z, pixy, piz);
            rjk.x = dist3(pj0, pj0z, pk0, pk0z);
            rij.y = dist3(pj1, pj1z, pixy, piz);
            rik.y = dist3(pk1, pk1z, pixy, piz);
            rjk.y = dist3(pj1, pj1z, pk1, pk1z);
        }
        {
            float2 pj2 = spxy[jc.z]; float pj2z = spz[jc.z];
            float2 pk2 = spxy[kc.z]; float pk2z = spz[kc.z];
            float2 pj3 = spxy[jc.w]; float pj3z = spz[jc.w];
            float2 pk3 = spxy[kc.w]; float pk3z = spz[kc.w];
            rij.z = dist3(pj2, pj2z, pixy, piz);
            rik.z = dist3(pk2, pk2z, pixy, piz);
            rjk.z = dist3(pj2, pj2z, pk2, pk2z);
            rij.w = dist3(pj3, pj3z, pixy, piz);
            rik.w = dist3(pk3, pk3z, pixy, piz);
            rjk.w = dist3(pj3, pj3z, pk3, pk3z);
        }

        // Wide streaming stores (minimal LSU issue cycles)
        __stcs(reinterpret_cast<float4*>(out + base),              rij);
        __stcs(reinterpret_cast<float4*>(out + TOTAL + base),      rik);
        __stcs(reinterpret_cast<float4*>(out + 2u * TOTAL + base), rjk);
    }
}

extern "C" void kernel_launch(void* const* d_in, const int* in_sizes, int n_in,
                              void* d_out, int out_size) {
    const float* pos = (const float*)d_in[0];
    const int*   nj  = (const int*)d_in[1];
    const int*   nk  = (const int*)d_in[2];
    float* out = (float*)d_out;

    dim3 grid(NB * NN / ROWS);
    TriplesDistances_kernel<<<grid, THREADS>>>(pos, nj, nk, out);
}

// round 15
// speedup vs baseline: 1.0727x; 1.0727x over previous
#include <cuda_runtime.h>

// TriplesDistances: B=16, N=512, A=1024
// inputs: positions f32 [B,N,3]; neighbors_j/k int32 [B,N,A]
// out layout: [r_ij | r_ik | r_jk], each B*N*A float32
#define NB 16
#define NN 512
#define NA 1024
#define THREADS 128
#define ROWS 4            // rows per work item (each CTA covers half-width rows)
#define HALFW 512         // elements of A covered per CTA per row

#define TOTAL (NB * NN * NA)   // 8388608, fits int32

// Single-instruction MUFU.SQRT: sqrt.approx(0)=0 handles the safe-norm zero
// case with no select; rel err ~2^-20 << 1e-3 tolerance.
__device__ __forceinline__ float fast_sqrt(float s) {
    float r;
    asm("sqrt.approx.f32 %0, %1;" : "=f"(r) : "f"(s));
    return r;
}

__device__ __forceinline__ float dist3(float2 axy, float az, float2 bxy, float bz) {
    float dx = axy.x - bxy.x;
    float dy = axy.y - bxy.y;
    float dz = az - bz;
    float s = fmaf(dx, dx, fmaf(dy, dy, dz * dz));
    return fast_sqrt(s);
}

__global__ __launch_bounds__(THREADS, 12)
void TriplesDistances_kernel(const float* __restrict__ pos,
                             const int* __restrict__ nj,
                             const int* __restrict__ nk,
                             float* __restrict__ out) {
    __shared__ float2 spxy[NN];  // 4 KB
    __shared__ float  spz[NN];   // 2 KB

    // Work item: (batch b, row group n0, half h)
    const unsigned blk   = blockIdx.x;                     // 0 .. 4095
    const unsigned h     = blk & 1u;                       // half of the A axis
    const unsigned item  = blk >> 1;                       // 0 .. 2047
    const unsigned b     = item / (NN / ROWS);             // batch
    const unsigned n0    = (item % (NN / ROWS)) * ROWS;    // first row
    const unsigned t     = threadIdx.x;

    const unsigned a0    = h * HALFW + t * 4u;
    const unsigned base0 = (b * NN + n0) * NA + a0;        // 32-bit safe

    // Row-0 index loads issued BEFORE staging: DRAM latency overlaps staging+sync
    int4 j4 = __ldcs(reinterpret_cast<const int4*>(nj + base0));
    int4 k4 = __ldcs(reinterpret_cast<const int4*>(nk + base0));

    // Cooperative stage of batch-b positions into smem (SoA), 128 thr x 4 iters
    const float* pb = pos + b * (NN * 3);
    #pragma unroll
    for (unsigned i = t; i < NN; i += THREADS) {
        float x = pb[i * 3 + 0];
        float y = pb[i * 3 + 1];
        float z = pb[i * 3 + 2];
        spxy[i] = make_float2(x, y);
        spz[i]  = z;
    }
    __syncthreads();

    #pragma unroll
    for (unsigned r = 0; r < ROWS; r++) {
        const unsigned base = base0 + r * NA;
        const int4 jc = j4, kc = k4;

        // Prefetch next row's indices while current gathers are in flight
        if (r + 1 < ROWS) {
            j4 = __ldcs(reinterpret_cast<const int4*>(nj + base + NA));
            k4 = __ldcs(reinterpret_cast<const int4*>(nk + base + NA));
        }

        const float2 pixy = spxy[n0 + r];
        const float  piz  = spz[n0 + r];

        float4 rij, rik, rjk;

        // Two-element gather hoisting: 8 independent LDS in flight per group
        {
            float2 pj0 = spxy[jc.x]; float pj0z = spz[jc.x];
            float2 pk0 = spxy[kc.x]; float pk0z = spz[kc.x];
            float2 pj1 = spxy[jc.y]; float pj1z = spz[jc.y];
            float2 pk1 = spxy[kc.y]; float pk1z = spz[kc.y];
            rij.x = dist3(pj0, pj0z, pixy, piz);
            rik.x = dist3(pk0, pk0z, pixy, piz);
            rjk.x = dist3(pj0, pj0z, pk0, pk0z);
            rij.y = dist3(pj1, pj1z, pixy, piz);
            rik.y = dist3(pk1, pk1z, pixy, piz);
            rjk.y = dist3(pj1, pj1z, pk1, pk1z);
        }
        {
            float2 pj2 = spxy[jc.z]; float pj2z = spz[jc.z];
            float2 pk2 = spxy[kc.z]; float pk2z = spz[kc.z];
            float2 pj3 = spxy[jc.w]; float pj3z = spz[jc.w];
            float2 pk3 = spxy[kc.w]; float pk3z = spz[kc.w];
            rij.z = dist3(pj2, pj2z, pixy, piz);
            rik.z = dist3(pk2, pk2z, pixy, piz);
            rjk.z = dist3(pj2, pj2z, pk2, pk2z);
            rij.w = dist3(pj3, pj3z, pixy, piz);
            rik.w = dist3(pk3, pk3z, pixy, piz);
            rjk.w = dist3(pj3, pj3z, pk3, pk3z);
        }

        // Wide streaming stores (minimal LSU issue cycles)
        __stcs(reinterpret_cast<float4*>(out + base),              rij);
        __stcs(reinterpret_cast<float4*>(out + TOTAL + base),      rik);
        __stcs(reinterpret_cast<float4*>(out + 2u * TOTAL + base), rjk);
    }
}

extern "C" void kernel_launch(void* const* d_in, const int* in_sizes, int n_in,
                              void* d_out, int out_size) {
    const float* pos = (const float*)d_in[0];
    const int*   nj  = (const int*)d_in[1];
    const int*   nk  = (const int*)d_in[2];
    float* out = (float*)d_out;

    dim3 grid((NB * NN / ROWS) * 2);   // 4096 CTAs of 128 threads
    TriplesDistances_kernel<<<grid, THREADS>>>(pos, nj, nk, out);
}